// round 1
// baseline (speedup 1.0000x reference)
#include <cuda_runtime.h>

#define NROWS 87382          // 87381 nodes + duplicated root
#define NLEAF 65536
#define LEAF_SOFF 21845

// ---------------- device scratch (no allocations allowed) ----------------
__device__ float g_T_iou[1000*768];
__device__ float g_T_f[1000*256];
__device__ float g_uiou0[768];
__device__ float g_uf0[1024];
__device__ float g_enc_h[(size_t)NROWS*256];
__device__ float g_cA[(size_t)NLEAF*256];
__device__ float g_cB[(size_t)16384*256];
__device__ float g_Giou[(size_t)16384*768];
__device__ float g_Gf[(size_t)16384*1024];
__device__ float g_sbuf[(size_t)4*NROWS];
__device__ float g_w[4*256];
__device__ float g_sum[4];
__device__ float g_max[4];
__device__ float g_hn_r[256];
__device__ float g_cn_r[256];
__device__ float g_qk_r[256];
__device__ float g_hn_c[4*256];
__device__ float g_cn_c[4*256];
__device__ float g_qk_c[4*256];
__device__ float g_hr[256];
__device__ float g_rows[20*256];

__device__ __forceinline__ float sigf(float x){ return 1.f/(1.f+__expf(-x)); }
__device__ __forceinline__ float tanhfast(float x){ return 1.f - 2.f/(__expf(2.f*x)+1.f); }

__device__ __forceinline__ void atomicMaxFloat(float* addr, float val){
    int old = __float_as_int(*addr);
    while (__int_as_float(old) < val) {
        int assumed = old;
        old = atomicCAS((int*)addr, assumed, __float_as_int(val));
        if (old == assumed) break;
    }
}

// ---------------- generic NT GEMM: C[M,N] = A[M,K] @ W[N,K]^T + bias(+bias2) ----------------
// 128x128 block tile, BK=16, 256 threads, 8x8 per thread.
__global__ void __launch_bounds__(256, 2) gemm_nt(
    const float* __restrict__ A, const float* __restrict__ W,
    const float* __restrict__ bias, const float* __restrict__ bias2,
    float* __restrict__ C, int M, int N, int K)
{
    __shared__ float As[16][128];
    __shared__ float Ws[16][128];
    const int tid  = threadIdx.x;
    const int m0   = blockIdx.y * 128;
    const int n0   = blockIdx.x * 128;
    const int trow = (tid >> 4) << 3;   // 0..120
    const int tcol = (tid & 15) << 3;
    const int lm   = tid >> 2;          // 0..63
    const int lk   = (tid & 3) << 2;    // 0,4,8,12

    float acc[8][8];
    #pragma unroll
    for (int i = 0; i < 8; i++)
        #pragma unroll
        for (int j = 0; j < 8; j++) acc[i][j] = 0.f;

    for (int k0 = 0; k0 < K; k0 += 16) {
        #pragma unroll
        for (int h = 0; h < 2; h++) {
            int m = m0 + lm + h*64;
            float4 v = make_float4(0.f,0.f,0.f,0.f);
            if (m < M) v = *reinterpret_cast<const float4*>(A + (size_t)m*K + k0 + lk);
            As[lk+0][lm+h*64] = v.x; As[lk+1][lm+h*64] = v.y;
            As[lk+2][lm+h*64] = v.z; As[lk+3][lm+h*64] = v.w;

            int n = n0 + lm + h*64;
            float4 w = make_float4(0.f,0.f,0.f,0.f);
            if (n < N) w = *reinterpret_cast<const float4*>(W + (size_t)n*K + k0 + lk);
            Ws[lk+0][lm+h*64] = w.x; Ws[lk+1][lm+h*64] = w.y;
            Ws[lk+2][lm+h*64] = w.z; Ws[lk+3][lm+h*64] = w.w;
        }
        __syncthreads();
        #pragma unroll
        for (int kk = 0; kk < 16; kk++) {
            float ra[8], rw[8];
            #pragma unroll
            for (int i = 0; i < 8; i++) ra[i] = As[kk][trow+i];
            #pragma unroll
            for (int j = 0; j < 8; j++) rw[j] = Ws[kk][tcol+j];
            #pragma unroll
            for (int i = 0; i < 8; i++)
                #pragma unroll
                for (int j = 0; j < 8; j++) acc[i][j] += ra[i]*rw[j];
        }
        __syncthreads();
    }
    #pragma unroll
    for (int i = 0; i < 8; i++) {
        int m = m0 + trow + i;
        if (m >= M) break;
        #pragma unroll
        for (int j = 0; j < 8; j++) {
            int n = n0 + tcol + j;
            float b = 0.f;
            if (bias)  b += bias[n];
            if (bias2) b += bias2[n];
            C[(size_t)m*N + n] = acc[i][j] + b;
        }
    }
}

// ---------------- leaf constants: h0 @ U_iou^T, h0 @ U_f^T + b_uf ----------------
__global__ void leaf_consts(const float* __restrict__ h0, const float* __restrict__ U_iou,
                            const float* __restrict__ U_f, const float* __restrict__ b_uf)
{
    __shared__ float sh[1024];
    int tid = threadIdx.x;
    for (int i = tid; i < 1024; i += 256) sh[i] = h0[i];
    __syncthreads();
    int j = blockIdx.x * 256 + tid;   // 0..1791
    if (j < 768) {
        const float* u = U_iou + (size_t)j*1024;
        float acc = 0.f;
        for (int k = 0; k < 1024; k++) acc += sh[k]*u[k];
        g_uiou0[j] = acc;
    } else if (j < 1792) {
        int jj = j - 768;
        const float* u = U_f + (size_t)jj*1024;
        float acc = b_uf[jj];
        for (int k = 0; k < 1024; k++) acc += sh[k]*u[k];
        g_uf0[jj] = acc;
    }
}

// ---------------- leaf level: pure gather + elementwise ----------------
__global__ void leaf_kernel(const int* __restrict__ src, const float* __restrict__ c0)
{
    int b = blockIdx.x, j = threadIdx.x;
    int id = src[LEAF_SOFF + b];
    const float* T = g_T_iou + (size_t)id*768;
    float i = sigf(T[j]       + g_uiou0[j]);
    float o = sigf(T[256+j]   + g_uiou0[256+j]);
    float u = tanhfast(T[512+j] + g_uiou0[512+j]);
    float tf = g_T_f[(size_t)id*256 + j];
    float c = i*u;
    #pragma unroll
    for (int a = 0; a < 4; a++) {
        float f = sigf(g_uf0[a*256+j] + tf);
        c += f * c0[a*256+j];
    }
    g_enc_h[(size_t)b*256 + j] = o * tanhfast(c);
    g_cA[(size_t)b*256 + j]   = c;
}

// ---------------- interior level: combine GEMM results + gates ----------------
__global__ void level_ew(const int* __restrict__ src, int soff,
                         const float* __restrict__ cprev, float* __restrict__ cout,
                         int rowoff, int dup)
{
    int b = blockIdx.x, j = threadIdx.x;
    int id = src[soff + b];
    const float* T  = g_T_iou + (size_t)id*768;
    const float* Gi = g_Giou  + (size_t)b*768;
    float i = sigf(Gi[j]       + T[j]);
    float o = sigf(Gi[256+j]   + T[256+j]);
    float u = tanhfast(Gi[512+j] + T[512+j]);
    float tf = g_T_f[(size_t)id*256 + j];
    const float* Gf = g_Gf + (size_t)b*1024;
    float c = i*u;
    #pragma unroll
    for (int a = 0; a < 4; a++) {
        float f = sigf(Gf[a*256+j] + tf);
        c += f * cprev[(size_t)(4*b+a)*256 + j];
    }
    float h = o * tanhfast(c);
    g_enc_h[(size_t)(rowoff+b)*256 + j] = h;
    cout[(size_t)b*256 + j] = c;
    if (dup) g_enc_h[(size_t)(rowoff+1)*256 + j] = h;   // duplicate root row
}

// ---------------- decoder LSTM cell + fused q@Wq@Wk ----------------
__global__ void dec_prep(const float* __restrict__ emb, const int* __restrict__ tgt, int tbase,
                         const float* __restrict__ h_last, const float* __restrict__ c_last,
                         const float* __restrict__ W_ih, const float* __restrict__ b_ih,
                         const float* __restrict__ W_hh, const float* __restrict__ b_hh,
                         const float* __restrict__ Wq,   const float* __restrict__ Wk,
                         float* __restrict__ hn_out, float* __restrict__ cn_out,
                         float* __restrict__ qk_out)
{
    __shared__ float sx[256], sh[256], shn[256], sq[256];
    int j = threadIdx.x, bb = blockIdx.x;
    int sym = tgt[tbase + bb];
    sx[j] = emb[(size_t)sym*256 + j];
    sh[j] = h_last[j];
    __syncthreads();
    float g[4];
    #pragma unroll
    for (int p = 0; p < 4; p++) {
        int row = p*256 + j;
        const float* wi = W_ih + (size_t)row*256;
        const float* wh = W_hh + (size_t)row*256;
        float acc = b_ih[row] + b_hh[row];
        for (int k = 0; k < 256; k++) acc += sx[k]*wi[k] + sh[k]*wh[k];
        g[p] = acc;
    }
    float cn = sigf(g[1])*c_last[j] + sigf(g[0])*tanhfast(g[2]);
    float hn = sigf(g[3])*tanhfast(cn);
    shn[j] = hn;
    hn_out[bb*256+j] = hn;
    cn_out[bb*256+j] = cn;
    __syncthreads();
    const float* wq = Wq + (size_t)j*256;
    float q = 0.f;
    for (int k = 0; k < 256; k++) q += shn[k]*wq[k];
    sq[j] = q;
    __syncthreads();
    float qk = 0.f;
    for (int k = 0; k < 256; k++) qk += sq[k]*Wk[(size_t)k*256 + j];
    qk_out[bb*256+j] = qk;
}

__global__ void attn_init()
{
    int t = threadIdx.x;
    for (int i = t; i < 4*256; i += 256) g_w[i] = 0.f;
    if (t < 4) { g_sum[t] = 0.f; g_max[t] = -1e30f; }
}

// scores pass: s[b][n] = qk_b . enc_h[n], plus global max
#define SROWS 512
__global__ void attn_scores(const float* __restrict__ qk, int B)
{
    __shared__ float sqk[4*256];
    __shared__ float wmax[8*4];
    int tid = threadIdx.x;
    for (int i = tid; i < B*256; i += 256) sqk[i] = qk[i];
    __syncthreads();
    int warp = tid >> 5, lane = tid & 31;
    int start = blockIdx.x * SROWS;
    int end = min(NROWS, start + SROWS);
    float lmax[4] = {-1e30f,-1e30f,-1e30f,-1e30f};
    for (int r = start + warp; r < end; r += 8) {
        const float4* eh = reinterpret_cast<const float4*>(g_enc_h + (size_t)r*256) + lane*2;
        float4 v0 = eh[0], v1 = eh[1];
        #pragma unroll 4
        for (int b = 0; b < 4; b++) {
            if (b >= B) break;
            const float* q = sqk + b*256 + lane*8;
            float acc = v0.x*q[0]+v0.y*q[1]+v0.z*q[2]+v0.w*q[3]
                      + v1.x*q[4]+v1.y*q[5]+v1.z*q[6]+v1.w*q[7];
            #pragma unroll
            for (int off = 16; off; off >>= 1) acc += __shfl_xor_sync(0xffffffffu, acc, off);
            if (lane == 0) g_sbuf[(size_t)b*NROWS + r] = acc;
            lmax[b] = fmaxf(lmax[b], acc);
        }
    }
    if (lane == 0)
        for (int b = 0; b < 4; b++) wmax[warp*4+b] = lmax[b];
    __syncthreads();
    if (tid < B) {
        float m = -1e30f;
        for (int w = 0; w < 8; w++) m = fmaxf(m, wmax[w*4+tid]);
        atomicMaxFloat(&g_max[tid], m);
    }
}

// weighted pass: w[b][d] = sum_n exp(s-smax) * enc_h[n][d]; sum[b] = sum exp
#define WROWS 256
__global__ void attn_weighted(int B)
{
    __shared__ float se[4*64];
    int tid = threadIdx.x;
    float mx[4] = {0,0,0,0};
    for (int b = 0; b < B; b++) mx[b] = g_max[b];
    float wloc[4] = {0,0,0,0};
    float ssum = 0.f;
    int start = blockIdx.x * WROWS;
    int end = min(NROWS, start + WROWS);
    for (int c0 = start; c0 < end; c0 += 64) {
        int nr = end - c0; if (nr > 64) nr = 64;
        __syncthreads();
        if (tid < 64*B) {
            int b = tid >> 6, i = tid & 63;
            se[tid] = (i < nr) ? __expf(g_sbuf[(size_t)b*NROWS + c0 + i] - mx[b]) : 0.f;
        }
        __syncthreads();
        for (int i = 0; i < nr; i++) {
            float x = g_enc_h[(size_t)(c0+i)*256 + tid];
            #pragma unroll 4
            for (int b = 0; b < 4; b++) {
                if (b >= B) break;
                wloc[b] += se[b*64+i]*x;
            }
        }
        if (tid < B)
            for (int i = 0; i < nr; i++) ssum += se[tid*64+i];
    }
    for (int b = 0; b < B; b++) atomicAdd(&g_w[b*256+tid], wloc[b]);
    if (tid < B) atomicAdd(&g_sum[tid], ssum);
}

// finalize: ctx = (w/sum)@Wv^T ; h_out = [hn|ctx]@lin_W^T + lin_b ; rows += pos_emb
__global__ void dec_fin(const float* __restrict__ hn, int is_root,
                        const float* __restrict__ Wv, const float* __restrict__ linW,
                        const float* __restrict__ linb, const float* __restrict__ pos)
{
    __shared__ float swb[256], sctx[256], shn[256];
    int b = blockIdx.x, j = threadIdx.x;
    swb[j] = g_w[b*256+j] / g_sum[b];
    shn[j] = hn[b*256+j];
    __syncthreads();
    const float* wv = Wv + (size_t)j*256;
    float acc = 0.f;
    for (int k = 0; k < 256; k++) acc += swb[k]*wv[k];
    sctx[j] = acc;
    __syncthreads();
    const float* lw = linW + (size_t)j*512;
    float ho = linb[j];
    for (int k = 0; k < 256; k++) ho += shn[k]*lw[k];
    for (int k = 0; k < 256; k++) ho += sctx[k]*lw[256+k];
    if (is_root) {
        g_hr[j] = ho;
        #pragma unroll
        for (int a = 0; a < 4; a++) g_rows[a*256+j] = ho + pos[a*256+j];
    } else {
        #pragma unroll
        for (int a = 0; a < 4; a++) g_rows[(4 + b*4 + a)*256 + j] = ho + pos[a*256+j];
    }
}

// final vocab projection: out[20,1000] = rows @ W_out^T + b_out
__global__ void out_proj(const float* __restrict__ Wout, const float* __restrict__ bout,
                         float* __restrict__ out)
{
    __shared__ float sr[256];
    int j = threadIdx.x;
    sr[j] = g_rows[blockIdx.x*256 + j];
    __syncthreads();
    for (int n = j; n < 1000; n += 256) {
        const float* w = Wout + (size_t)n*256;
        float acc = bout[n];
        for (int k = 0; k < 256; k++) acc += sr[k]*w[k];
        out[blockIdx.x*1000 + n] = acc;
    }
}

// ---------------------------------------------------------------------------
extern "C" void kernel_launch(void* const* d_in, const int* in_sizes, int n_in,
                              void* d_out, int out_size)
{
    const int*   src    = (const int*)  d_in[0];
    const int*   tgt    = (const int*)  d_in[1];
    const float* emb    = (const float*)d_in[2];
    const float* h0     = (const float*)d_in[3];
    const float* c0     = (const float*)d_in[4];
    const float* W_iou  = (const float*)d_in[5];
    const float* b_iou  = (const float*)d_in[6];
    const float* U_iou  = (const float*)d_in[7];
    const float* b_uiou = (const float*)d_in[8];
    const float* W_f    = (const float*)d_in[9];
    const float* b_wf   = (const float*)d_in[10];
    const float* U_f    = (const float*)d_in[11];
    const float* b_uf   = (const float*)d_in[12];
    const float* W_ih   = (const float*)d_in[13];
    const float* b_ih   = (const float*)d_in[14];
    const float* W_hh   = (const float*)d_in[15];
    const float* b_hh   = (const float*)d_in[16];
    const float* Wq     = (const float*)d_in[17];
    const float* Wk     = (const float*)d_in[18];
    const float* Wv     = (const float*)d_in[19];
    const float* lin_W  = (const float*)d_in[20];
    const float* lin_b  = (const float*)d_in[21];
    const float* pos    = (const float*)d_in[22];
    const float* W_out  = (const float*)d_in[23];
    const float* b_out  = (const float*)d_in[24];
    float* out = (float*)d_out;

    float *pTiou,*pTf,*pEnc,*pCA,*pCB,*pGiou,*pGf;
    float *pHnR,*pCnR,*pQkR,*pHnC,*pCnC,*pQkC,*pHr;
    cudaGetSymbolAddress((void**)&pTiou, g_T_iou);
    cudaGetSymbolAddress((void**)&pTf,   g_T_f);
    cudaGetSymbolAddress((void**)&pEnc,  g_enc_h);
    cudaGetSymbolAddress((void**)&pCA,   g_cA);
    cudaGetSymbolAddress((void**)&pCB,   g_cB);
    cudaGetSymbolAddress((void**)&pGiou, g_Giou);
    cudaGetSymbolAddress((void**)&pGf,   g_Gf);
    cudaGetSymbolAddress((void**)&pHnR,  g_hn_r);
    cudaGetSymbolAddress((void**)&pCnR,  g_cn_r);
    cudaGetSymbolAddress((void**)&pQkR,  g_qk_r);
    cudaGetSymbolAddress((void**)&pHnC,  g_hn_c);
    cudaGetSymbolAddress((void**)&pCnC,  g_cn_c);
    cudaGetSymbolAddress((void**)&pQkC,  g_qk_c);
    cudaGetSymbolAddress((void**)&pHr,   g_hr);

    static const int pow4[10] = {1,4,16,64,256,1024,4096,16384,65536,262144};
    auto rowoff = [&](int l){ return (262144 - pow4[l+1]) / 3; };
    auto soff   = [&](int l){ return (pow4[l] - 1) / 3; };

    // 1) per-vocab tables (biases folded in)
    gemm_nt<<<dim3(6, 8), 256>>>(emb, W_iou, b_iou, b_uiou, pTiou, 1000, 768, 256);
    gemm_nt<<<dim3(2, 8), 256>>>(emb, W_f,   b_wf,  nullptr, pTf,   1000, 256, 256);

    // 2) leaf constants + leaf level (matmul-free)
    leaf_consts<<<7, 256>>>(h0, U_iou, U_f, b_uf);
    leaf_kernel<<<NLEAF, 256>>>(src, c0);

    // 3) interior levels bottom-up
    float* cprev = pCA;
    float* cout  = pCB;
    for (int l = 7; l >= 0; l--) {
        int B = pow4[l];
        const float* Ap = pEnc + (size_t)rowoff(l+1)*256;  // children h, viewed (B,1024)
        gemm_nt<<<dim3(6, (B+127)/128), 256>>>(Ap, U_iou, nullptr, nullptr, pGiou, B, 768,  1024);
        gemm_nt<<<dim3(8, (B+127)/128), 256>>>(Ap, U_f,   b_uf,    nullptr, pGf,   B, 1024, 1024);
        level_ew<<<B, 256>>>(src, soff(l), cprev, cout, rowoff(l), (l == 0) ? 1 : 0);
        float* t = cprev; cprev = cout; cout = t;
    }
    // cprev now holds root c (row 0)

    int sgrid = (NROWS + SROWS - 1) / SROWS;
    int wgrid = (NROWS + WROWS - 1) / WROWS;

    // 4) root decode step
    attn_init<<<1, 256>>>();
    dec_prep<<<1, 256>>>(emb, tgt, 0, pEnc + (size_t)(NROWS-1)*256, cprev,
                         W_ih, b_ih, W_hh, b_hh, Wq, Wk, pHnR, pCnR, pQkR);
    attn_scores<<<sgrid, 256>>>(pQkR, 1);
    attn_weighted<<<wgrid, 256>>>(1);
    dec_fin<<<1, 256>>>(pHnR, 1, Wv, lin_W, lin_b, pos);

    // 5) child decode step (B=4)
    attn_init<<<1, 256>>>();
    dec_prep<<<4, 256>>>(emb, tgt, 1, pHr, pCnR,
                         W_ih, b_ih, W_hh, b_hh, Wq, Wk, pHnC, pCnC, pQkC);
    attn_scores<<<sgrid, 256>>>(pQkC, 4);
    attn_weighted<<<wgrid, 256>>>(4);
    dec_fin<<<4, 256>>>(pHnC, 0, Wv, lin_W, lin_b, pos);

    // 6) vocab projection
    out_proj<<<20, 256>>>(W_out, b_out, out);
}

// round 2
// speedup vs baseline: 1.8103x; 1.8103x over previous
#include <cuda_runtime.h>
#include <cstdint>

#define NROWS 87382          // 87381 nodes + duplicated root
#define NLEAF 65536
#define LEAF_SOFF 21845

// ---------------- device scratch (no allocations allowed) ----------------
__device__ float g_T_iou[1000*768];
__device__ float g_T_f[1000*256];
__device__ float g_uiou0[768];
__device__ float g_uf0[1024];
__device__ float g_U[1792*1024];            // packed [U_iou; U_f]
__device__ float g_enc_h[(size_t)NROWS*256];
__device__ float g_cA[(size_t)NLEAF*256];
__device__ float g_cB[(size_t)16384*256];
__device__ float g_G[(size_t)16384*1792];   // combined gate preactivations
__device__ float g_sbuf[(size_t)4*NROWS];
__device__ float g_w[4*256];
__device__ float g_sum[4];
__device__ float g_max[4];
__device__ float g_hn_r[256];
__device__ float g_cn_r[256];
__device__ float g_qk_r[256];
__device__ float g_hn_c[4*256];
__device__ float g_cn_c[4*256];
__device__ float g_qk_c[4*256];
__device__ float g_hr[256];
__device__ float g_rows[20*256];

__device__ __forceinline__ float sigf(float x){ return 1.f/(1.f+__expf(-x)); }
__device__ __forceinline__ float tanhfast(float x){ return 1.f - 2.f/(__expf(2.f*x)+1.f); }

__device__ __forceinline__ float to_tf32(float x){
    uint32_t r;
    asm("cvt.rna.tf32.f32 %0, %1;" : "=r"(r) : "f"(x));
    return __uint_as_float(r);
}

__device__ __forceinline__ void atomicMaxFloat(float* addr, float val){
    int old = __float_as_int(*addr);
    while (__int_as_float(old) < val) {
        int assumed = old;
        old = atomicCAS((int*)addr, assumed, __float_as_int(val));
        if (old == assumed) break;
    }
}

// ---------------- pack [U_iou; U_f] into one 1792x1024 matrix ----------------
__global__ void pack_U(const float* __restrict__ U_iou, const float* __restrict__ U_f)
{
    int idx = blockIdx.x * 256 + threadIdx.x;            // over 1792*1024/4 float4s
    if (idx >= 1792*1024/4) return;
    int r = idx / 256;          // row (k index within float4 handled by vector)
    int c4 = idx % 256;         // float4 column
    const float4* srcp;
    if (r < 768) srcp = reinterpret_cast<const float4*>(U_iou + (size_t)r*1024) + c4;
    else         srcp = reinterpret_cast<const float4*>(U_f   + (size_t)(r-768)*1024) + c4;
    reinterpret_cast<float4*>(g_U + (size_t)r*1024)[c4] = *srcp;
}

// ---------------- tf32 tensor-core GEMM: C[M,1792] = A[M,1024] @ U^T ----------------
// Block tile 256(M) x 128(N), BK=16, 8 warps of 64x64 (4m x 2n).
#define GK 1024
#define GN 1792
__global__ void __launch_bounds__(256, 1) gemm_tf32(
    const float* __restrict__ A, float* __restrict__ C, int M)
{
    __shared__ float As[16][264];   // [k][m]  pad 264 -> conflict-free frags
    __shared__ float Ws[16][136];   // [k][n]

    const int tid  = threadIdx.x;
    const int lane = tid & 31;
    const int wid  = tid >> 5;
    const int warp_m = wid & 3;          // 0..3 -> 64-row slab
    const int warp_n = wid >> 2;         // 0..1 -> 64-col slab
    const int g  = lane >> 2;            // groupID 0..7
    const int tq = lane & 3;             // thread-in-group

    const int m0 = blockIdx.y * 256;
    const int n0 = blockIdx.x * 128;

    // global load mapping
    const int am_row = m0 + tid;                  // A row this thread loads
    const bool am = am_row < M;
    const float* Arow = A + (size_t)am_row * GK;
    const int wn  = n0 + (tid & 127);
    const int wkh = (tid >> 7) * 8;               // 0 or 8
    const float* Wrow = g_U + (size_t)wn * GK + wkh;

    float4 pa[4], pw[2];
    // preload iter 0
    #pragma unroll
    for (int i = 0; i < 4; i++)
        pa[i] = am ? *reinterpret_cast<const float4*>(Arow + i*4)
                   : make_float4(0.f,0.f,0.f,0.f);
    #pragma unroll
    for (int j = 0; j < 2; j++)
        pw[j] = *reinterpret_cast<const float4*>(Wrow + j*4);

    float acc[4][8][4];
    #pragma unroll
    for (int mt = 0; mt < 4; mt++)
        #pragma unroll
        for (int nt = 0; nt < 8; nt++)
            #pragma unroll
            for (int q = 0; q < 4; q++) acc[mt][nt][q] = 0.f;

    for (int k0 = 0; k0 < GK; k0 += 16) {
        // commit current regs to shared (tf32-rounded)
        #pragma unroll
        for (int i = 0; i < 4; i++) {
            As[i*4+0][tid] = to_tf32(pa[i].x);
            As[i*4+1][tid] = to_tf32(pa[i].y);
            As[i*4+2][tid] = to_tf32(pa[i].z);
            As[i*4+3][tid] = to_tf32(pa[i].w);
        }
        #pragma unroll
        for (int j = 0; j < 2; j++) {
            Ws[wkh+j*4+0][tid & 127] = to_tf32(pw[j].x);
            Ws[wkh+j*4+1][tid & 127] = to_tf32(pw[j].y);
            Ws[wkh+j*4+2][tid & 127] = to_tf32(pw[j].z);
            Ws[wkh+j*4+3][tid & 127] = to_tf32(pw[j].w);
        }
        __syncthreads();

        // prefetch next iter
        if (k0 + 16 < GK) {
            const float* An = Arow + k0 + 16;
            #pragma unroll
            for (int i = 0; i < 4; i++)
                pa[i] = am ? *reinterpret_cast<const float4*>(An + i*4)
                           : make_float4(0.f,0.f,0.f,0.f);
            const float* Wn = Wrow + k0 + 16;
            #pragma unroll
            for (int j = 0; j < 2; j++)
                pw[j] = *reinterpret_cast<const float4*>(Wn + j*4);
        }

        // compute 2 k-steps of 8
        #pragma unroll
        for (int kk = 0; kk < 16; kk += 8) {
            uint32_t af[4][4], bf[8][2];
            #pragma unroll
            for (int mt = 0; mt < 4; mt++) {
                int rm = warp_m*64 + mt*16 + g;
                af[mt][0] = __float_as_uint(As[kk+tq  ][rm  ]);
                af[mt][1] = __float_as_uint(As[kk+tq  ][rm+8]);
                af[mt][2] = __float_as_uint(As[kk+tq+4][rm  ]);
                af[mt][3] = __float_as_uint(As[kk+tq+4][rm+8]);
            }
            #pragma unroll
            for (int nt = 0; nt < 8; nt++) {
                int cn = warp_n*64 + nt*8 + g;
                bf[nt][0] = __float_as_uint(Ws[kk+tq  ][cn]);
                bf[nt][1] = __float_as_uint(Ws[kk+tq+4][cn]);
            }
            #pragma unroll
            for (int mt = 0; mt < 4; mt++)
                #pragma unroll
                for (int nt = 0; nt < 8; nt++) {
                    asm volatile(
                        "mma.sync.aligned.m16n8k8.row.col.f32.tf32.tf32.f32 "
                        "{%0,%1,%2,%3}, {%4,%5,%6,%7}, {%8,%9}, {%0,%1,%2,%3};"
                        : "+f"(acc[mt][nt][0]), "+f"(acc[mt][nt][1]),
                          "+f"(acc[mt][nt][2]), "+f"(acc[mt][nt][3])
                        : "r"(af[mt][0]), "r"(af[mt][1]), "r"(af[mt][2]), "r"(af[mt][3]),
                          "r"(bf[nt][0]), "r"(bf[nt][1]));
                }
        }
        __syncthreads();
    }

    // epilogue
    #pragma unroll
    for (int mt = 0; mt < 4; mt++) {
        int m = m0 + warp_m*64 + mt*16 + g;
        #pragma unroll
        for (int nt = 0; nt < 8; nt++) {
            int n = n0 + warp_n*64 + nt*8 + tq*2;
            if (m < M)
                *reinterpret_cast<float2*>(C + (size_t)m*GN + n)
                    = make_float2(acc[mt][nt][0], acc[mt][nt][1]);
            if (m + 8 < M)
                *reinterpret_cast<float2*>(C + (size_t)(m+8)*GN + n)
                    = make_float2(acc[mt][nt][2], acc[mt][nt][3]);
        }
    }
}

// ---------------- small-M GEMM (M<=64): warp-per-column, fp32 ----------------
__global__ void small_gemm(const float* __restrict__ A, float* __restrict__ C)
{
    __shared__ float sh[1024];
    int tid = threadIdx.x, lane = tid & 31, wid = tid >> 5;
    int m = blockIdx.y;
    for (int i = tid; i < 256; i += 256)
        reinterpret_cast<float4*>(sh)[i] = reinterpret_cast<const float4*>(A + (size_t)m*1024)[i];
    __syncthreads();
    int ntile = blockIdx.x * 256;
    for (int n = ntile + wid; n < ntile + 256 && n < GN; n += 8) {
        const float4* u = reinterpret_cast<const float4*>(g_U + (size_t)n*1024);
        float acc = 0.f;
        #pragma unroll
        for (int i = 0; i < 8; i++) {
            float4 uv = u[lane + i*32];
            float4 hv = reinterpret_cast<const float4*>(sh)[lane + i*32];
            acc += uv.x*hv.x + uv.y*hv.y + uv.z*hv.z + uv.w*hv.w;
        }
        #pragma unroll
        for (int off = 16; off; off >>= 1) acc += __shfl_xor_sync(0xffffffffu, acc, off);
        if (lane == 0) C[(size_t)m*GN + n] = acc;
    }
}

// ---------------- SIMT NT GEMM (kept for the small vocab tables) ----------------
__global__ void __launch_bounds__(256, 2) gemm_nt(
    const float* __restrict__ A, const float* __restrict__ W,
    const float* __restrict__ bias, const float* __restrict__ bias2,
    float* __restrict__ C, int M, int N, int K)
{
    __shared__ float As[16][128];
    __shared__ float Ws[16][128];
    const int tid  = threadIdx.x;
    const int m0   = blockIdx.y * 128;
    const int n0   = blockIdx.x * 128;
    const int trow = (tid >> 4) << 3;
    const int tcol = (tid & 15) << 3;
    const int lm   = tid >> 2;
    const int lk   = (tid & 3) << 2;

    float acc[8][8];
    #pragma unroll
    for (int i = 0; i < 8; i++)
        #pragma unroll
        for (int j = 0; j < 8; j++) acc[i][j] = 0.f;

    for (int k0 = 0; k0 < K; k0 += 16) {
        #pragma unroll
        for (int h = 0; h < 2; h++) {
            int m = m0 + lm + h*64;
            float4 v = make_float4(0.f,0.f,0.f,0.f);
            if (m < M) v = *reinterpret_cast<const float4*>(A + (size_t)m*K + k0 + lk);
            As[lk+0][lm+h*64] = v.x; As[lk+1][lm+h*64] = v.y;
            As[lk+2][lm+h*64] = v.z; As[lk+3][lm+h*64] = v.w;

            int n = n0 + lm + h*64;
            float4 w = make_float4(0.f,0.f,0.f,0.f);
            if (n < N) w = *reinterpret_cast<const float4*>(W + (size_t)n*K + k0 + lk);
            Ws[lk+0][lm+h*64] = w.x; Ws[lk+1][lm+h*64] = w.y;
            Ws[lk+2][lm+h*64] = w.z; Ws[lk+3][lm+h*64] = w.w;
        }
        __syncthreads();
        #pragma unroll
        for (int kk = 0; kk < 16; kk++) {
            float ra[8], rw[8];
            #pragma unroll
            for (int i = 0; i < 8; i++) ra[i] = As[kk][trow+i];
            #pragma unroll
            for (int j = 0; j < 8; j++) rw[j] = Ws[kk][tcol+j];
            #pragma unroll
            for (int i = 0; i < 8; i++)
                #pragma unroll
                for (int j = 0; j < 8; j++) acc[i][j] += ra[i]*rw[j];
        }
        __syncthreads();
    }
    #pragma unroll
    for (int i = 0; i < 8; i++) {
        int m = m0 + trow + i;
        if (m >= M) break;
        #pragma unroll
        for (int j = 0; j < 8; j++) {
            int n = n0 + tcol + j;
            float b = 0.f;
            if (bias)  b += bias[n];
            if (bias2) b += bias2[n];
            C[(size_t)m*N + n] = acc[i][j] + b;
        }
    }
}

// ---------------- leaf constants: h0 @ U_iou^T, h0 @ U_f^T + b_uf ----------------
__global__ void leaf_consts(const float* __restrict__ h0, const float* __restrict__ U_iou,
                            const float* __restrict__ U_f, const float* __restrict__ b_uf)
{
    __shared__ float sh[1024];
    int tid = threadIdx.x;
    for (int i = tid; i < 1024; i += 256) sh[i] = h0[i];
    __syncthreads();
    int j = blockIdx.x * 256 + tid;
    if (j < 768) {
        const float* u = U_iou + (size_t)j*1024;
        float acc = 0.f;
        for (int k = 0; k < 1024; k++) acc += sh[k]*u[k];
        g_uiou0[j] = acc;
    } else if (j < 1792) {
        int jj = j - 768;
        const float* u = U_f + (size_t)jj*1024;
        float acc = b_uf[jj];
        for (int k = 0; k < 1024; k++) acc += sh[k]*u[k];
        g_uf0[jj] = acc;
    }
}

// ---------------- leaf level: pure gather + elementwise ----------------
__global__ void leaf_kernel(const int* __restrict__ src, const float* __restrict__ c0)
{
    int b = blockIdx.x, j = threadIdx.x;
    int id = src[LEAF_SOFF + b];
    const float* T = g_T_iou + (size_t)id*768;
    float i = sigf(T[j]       + g_uiou0[j]);
    float o = sigf(T[256+j]   + g_uiou0[256+j]);
    float u = tanhfast(T[512+j] + g_uiou0[512+j]);
    float tf = g_T_f[(size_t)id*256 + j];
    float c = i*u;
    #pragma unroll
    for (int a = 0; a < 4; a++) {
        float f = sigf(g_uf0[a*256+j] + tf);
        c += f * c0[a*256+j];
    }
    g_enc_h[(size_t)b*256 + j] = o * tanhfast(c);
    g_cA[(size_t)b*256 + j]   = c;
}

// ---------------- interior level: combine GEMM result + gates ----------------
__global__ void level_ew(const int* __restrict__ src, int soff,
                         const float* __restrict__ cprev, float* __restrict__ cout,
                         int rowoff, int dup, const float* __restrict__ b_uf)
{
    int b = blockIdx.x, j = threadIdx.x;
    int id = src[soff + b];
    const float* T = g_T_iou + (size_t)id*768;
    const float* G = g_G + (size_t)b*1792;
    float i = sigf(G[j]       + T[j]);
    float o = sigf(G[256+j]   + T[256+j]);
    float u = tanhfast(G[512+j] + T[512+j]);
    float tf = g_T_f[(size_t)id*256 + j];
    float c = i*u;
    #pragma unroll
    for (int a = 0; a < 4; a++) {
        float f = sigf(G[768 + a*256 + j] + b_uf[a*256+j] + tf);
        c += f * cprev[(size_t)(4*b+a)*256 + j];
    }
    float h = o * tanhfast(c);
    g_enc_h[(size_t)(rowoff+b)*256 + j] = h;
    cout[(size_t)b*256 + j] = c;
    if (dup) g_enc_h[(size_t)(rowoff+1)*256 + j] = h;   // duplicate root row
}

// ---------------- decoder LSTM cell + fused q@Wq@Wk ----------------
__global__ void dec_prep(const float* __restrict__ emb, const int* __restrict__ tgt, int tbase,
                         const float* __restrict__ h_last, const float* __restrict__ c_last,
                         const float* __restrict__ W_ih, const float* __restrict__ b_ih,
                         const float* __restrict__ W_hh, const float* __restrict__ b_hh,
                         const float* __restrict__ Wq,   const float* __restrict__ Wk,
                         float* __restrict__ hn_out, float* __restrict__ cn_out,
                         float* __restrict__ qk_out)
{
    __shared__ float sx[256], sh[256], shn[256], sq[256];
    int j = threadIdx.x, bb = blockIdx.x;
    int sym = tgt[tbase + bb];
    sx[j] = emb[(size_t)sym*256 + j];
    sh[j] = h_last[j];
    __syncthreads();
    float g[4];
    #pragma unroll
    for (int p = 0; p < 4; p++) {
        int row = p*256 + j;
        const float* wi = W_ih + (size_t)row*256;
        const float* wh = W_hh + (size_t)row*256;
        float acc = b_ih[row] + b_hh[row];
        for (int k = 0; k < 256; k++) acc += sx[k]*wi[k] + sh[k]*wh[k];
        g[p] = acc;
    }
    float cn = sigf(g[1])*c_last[j] + sigf(g[0])*tanhfast(g[2]);
    float hn = sigf(g[3])*tanhfast(cn);
    shn[j] = hn;
    hn_out[bb*256+j] = hn;
    cn_out[bb*256+j] = cn;
    __syncthreads();
    const float* wq = Wq + (size_t)j*256;
    float q = 0.f;
    for (int k = 0; k < 256; k++) q += shn[k]*wq[k];
    sq[j] = q;
    __syncthreads();
    float qk = 0.f;
    for (int k = 0; k < 256; k++) qk += sq[k]*Wk[(size_t)k*256 + j];
    qk_out[bb*256+j] = qk;
}

__global__ void attn_init()
{
    int t = threadIdx.x;
    for (int i = t; i < 4*256; i += 256) g_w[i] = 0.f;
    if (t < 4) { g_sum[t] = 0.f; g_max[t] = -1e30f; }
}

// scores pass: s[b][n] = qk_b . enc_h[n], plus global max
#define SROWS 512
__global__ void attn_scores(const float* __restrict__ qk, int B)
{
    __shared__ float sqk[4*256];
    __shared__ float wmax[8*4];
    int tid = threadIdx.x;
    for (int i = tid; i < B*256; i += 256) sqk[i] = qk[i];
    __syncthreads();
    int warp = tid >> 5, lane = tid & 31;
    int start = blockIdx.x * SROWS;
    int end = min(NROWS, start + SROWS);
    float lmax[4] = {-1e30f,-1e30f,-1e30f,-1e30f};
    for (int r = start + warp; r < end; r += 8) {
        const float4* eh = reinterpret_cast<const float4*>(g_enc_h + (size_t)r*256) + lane*2;
        float4 v0 = eh[0], v1 = eh[1];
        #pragma unroll 4
        for (int b = 0; b < 4; b++) {
            if (b >= B) break;
            const float* q = sqk + b*256 + lane*8;
            float acc = v0.x*q[0]+v0.y*q[1]+v0.z*q[2]+v0.w*q[3]
                      + v1.x*q[4]+v1.y*q[5]+v1.z*q[6]+v1.w*q[7];
            #pragma unroll
            for (int off = 16; off; off >>= 1) acc += __shfl_xor_sync(0xffffffffu, acc, off);
            if (lane == 0) g_sbuf[(size_t)b*NROWS + r] = acc;
            lmax[b] = fmaxf(lmax[b], acc);
        }
    }
    if (lane == 0)
        for (int b = 0; b < 4; b++) wmax[warp*4+b] = lmax[b];
    __syncthreads();
    if (tid < B) {
        float m = -1e30f;
        for (int w = 0; w < 8; w++) m = fmaxf(m, wmax[w*4+tid]);
        atomicMaxFloat(&g_max[tid], m);
    }
}

// weighted pass: w[b][d] = sum_n exp(s-smax) * enc_h[n][d]; sum[b] = sum exp
#define WROWS 256
__global__ void attn_weighted(int B)
{
    __shared__ float se[4*64];
    int tid = threadIdx.x;
    float mx[4] = {0,0,0,0};
    for (int b = 0; b < B; b++) mx[b] = g_max[b];
    float wloc[4] = {0,0,0,0};
    float ssum = 0.f;
    int start = blockIdx.x * WROWS;
    int end = min(NROWS, start + WROWS);
    for (int c0 = start; c0 < end; c0 += 64) {
        int nr = end - c0; if (nr > 64) nr = 64;
        __syncthreads();
        if (tid < 64*B) {
            int b = tid >> 6, i = tid & 63;
            se[tid] = (i < nr) ? __expf(g_sbuf[(size_t)b*NROWS + c0 + i] - mx[b]) : 0.f;
        }
        __syncthreads();
        for (int i = 0; i < nr; i++) {
            float x = g_enc_h[(size_t)(c0+i)*256 + tid];
            #pragma unroll 4
            for (int b = 0; b < 4; b++) {
                if (b >= B) break;
                wloc[b] += se[b*64+i]*x;
            }
        }
        if (tid < B)
            for (int i = 0; i < nr; i++) ssum += se[tid*64+i];
    }
    for (int b = 0; b < B; b++) atomicAdd(&g_w[b*256+tid], wloc[b]);
    if (tid < B) atomicAdd(&g_sum[tid], ssum);
}

// finalize: ctx = (w/sum)@Wv^T ; h_out = [hn|ctx]@lin_W^T + lin_b ; rows += pos_emb
__global__ void dec_fin(const float* __restrict__ hn, int is_root,
                        const float* __restrict__ Wv, const float* __restrict__ linW,
                        const float* __restrict__ linb, const float* __restrict__ pos)
{
    __shared__ float swb[256], sctx[256], shn[256];
    int b = blockIdx.x, j = threadIdx.x;
    swb[j] = g_w[b*256+j] / g_sum[b];
    shn[j] = hn[b*256+j];
    __syncthreads();
    const float* wv = Wv + (size_t)j*256;
    float acc = 0.f;
    for (int k = 0; k < 256; k++) acc += swb[k]*wv[k];
    sctx[j] = acc;
    __syncthreads();
    const float* lw = linW + (size_t)j*512;
    float ho = linb[j];
    for (int k = 0; k < 256; k++) ho += shn[k]*lw[k];
    for (int k = 0; k < 256; k++) ho += sctx[k]*lw[256+k];
    if (is_root) {
        g_hr[j] = ho;
        #pragma unroll
        for (int a = 0; a < 4; a++) g_rows[a*256+j] = ho + pos[a*256+j];
    } else {
        #pragma unroll
        for (int a = 0; a < 4; a++) g_rows[(4 + b*4 + a)*256 + j] = ho + pos[a*256+j];
    }
}

// final vocab projection: out[20,1000] = rows @ W_out^T + b_out
__global__ void out_proj(const float* __restrict__ Wout, const float* __restrict__ bout,
                         float* __restrict__ out)
{
    __shared__ float sr[256];
    int j = threadIdx.x;
    sr[j] = g_rows[blockIdx.x*256 + j];
    __syncthreads();
    for (int n = j; n < 1000; n += 256) {
        const float* w = Wout + (size_t)n*256;
        float acc = bout[n];
        for (int k = 0; k < 256; k++) acc += sr[k]*w[k];
        out[blockIdx.x*1000 + n] = acc;
    }
}

// ---------------------------------------------------------------------------
extern "C" void kernel_launch(void* const* d_in, const int* in_sizes, int n_in,
                              void* d_out, int out_size)
{
    const int*   src    = (const int*)  d_in[0];
    const int*   tgt    = (const int*)  d_in[1];
    const float* emb    = (const float*)d_in[2];
    const float* h0     = (const float*)d_in[3];
    const float* c0     = (const float*)d_in[4];
    const float* W_iou  = (const float*)d_in[5];
    const float* b_iou  = (const float*)d_in[6];
    const float* U_iou  = (const float*)d_in[7];
    const float* b_uiou = (const float*)d_in[8];
    const float* W_f    = (const float*)d_in[9];
    const float* b_wf   = (const float*)d_in[10];
    const float* U_f    = (const float*)d_in[11];
    const float* b_uf   = (const float*)d_in[12];
    const float* W_ih   = (const float*)d_in[13];
    const float* b_ih   = (const float*)d_in[14];
    const float* W_hh   = (const float*)d_in[15];
    const float* b_hh   = (const float*)d_in[16];
    const float* Wq     = (const float*)d_in[17];
    const float* Wk     = (const float*)d_in[18];
    const float* Wv     = (const float*)d_in[19];
    const float* lin_W  = (const float*)d_in[20];
    const float* lin_b  = (const float*)d_in[21];
    const float* pos    = (const float*)d_in[22];
    const float* W_out  = (const float*)d_in[23];
    const float* b_out  = (const float*)d_in[24];
    float* out = (float*)d_out;

    float *pTiou,*pTf,*pEnc,*pCA,*pCB,*pG;
    float *pHnR,*pCnR,*pQkR,*pHnC,*pCnC,*pQkC,*pHr;
    cudaGetSymbolAddress((void**)&pTiou, g_T_iou);
    cudaGetSymbolAddress((void**)&pTf,   g_T_f);
    cudaGetSymbolAddress((void**)&pEnc,  g_enc_h);
    cudaGetSymbolAddress((void**)&pCA,   g_cA);
    cudaGetSymbolAddress((void**)&pCB,   g_cB);
    cudaGetSymbolAddress((void**)&pG,    g_G);
    cudaGetSymbolAddress((void**)&pHnR,  g_hn_r);
    cudaGetSymbolAddress((void**)&pCnR,  g_cn_r);
    cudaGetSymbolAddress((void**)&pQkR,  g_qk_r);
    cudaGetSymbolAddress((void**)&pHnC,  g_hn_c);
    cudaGetSymbolAddress((void**)&pCnC,  g_cn_c);
    cudaGetSymbolAddress((void**)&pQkC,  g_qk_c);
    cudaGetSymbolAddress((void**)&pHr,   g_hr);

    static const int pow4[10] = {1,4,16,64,256,1024,4096,16384,65536,262144};
    auto rowoff = [&](int l){ return (262144 - pow4[l+1]) / 3; };
    auto soff   = [&](int l){ return (pow4[l] - 1) / 3; };

    // 1) per-vocab tables (biases folded in) + pack U
    gemm_nt<<<dim3(6, 8), 256>>>(emb, W_iou, b_iou, b_uiou, pTiou, 1000, 768, 256);
    gemm_nt<<<dim3(2, 8), 256>>>(emb, W_f,   b_wf,  nullptr, pTf,   1000, 256, 256);
    pack_U<<<(1792*1024/4 + 255)/256, 256>>>(U_iou, U_f);

    // 2) leaf constants + leaf level (matmul-free)
    leaf_consts<<<7, 256>>>(h0, U_iou, U_f, b_uf);
    leaf_kernel<<<NLEAF, 256>>>(src, c0);

    // 3) interior levels bottom-up (tensor-core GEMM + fused gates)
    float* cprev = pCA;
    float* cout  = pCB;
    for (int l = 7; l >= 0; l--) {
        int B = pow4[l];
        const float* Ap = pEnc + (size_t)rowoff(l+1)*256;  // children h, viewed (B,1024)
        if (B >= 256)
            gemm_tf32<<<dim3(14, (B+255)/256), 256>>>(Ap, pG, B);
        else
            small_gemm<<<dim3(7, B), 256>>>(Ap, pG);
        level_ew<<<B, 256>>>(src, soff(l), cprev, cout, rowoff(l), (l == 0) ? 1 : 0, b_uf);
        float* t = cprev; cprev = cout; cout = t;
    }
    // cprev now holds root c (row 0)

    int sgrid = (NROWS + SROWS - 1) / SROWS;
    int wgrid = (NROWS + WROWS - 1) / WROWS;

    // 4) root decode step
    attn_init<<<1, 256>>>();
    dec_prep<<<1, 256>>>(emb, tgt, 0, pEnc + (size_t)(NROWS-1)*256, cprev,
                         W_ih, b_ih, W_hh, b_hh, Wq, Wk, pHnR, pCnR, pQkR);
    attn_scores<<<sgrid, 256>>>(pQkR, 1);
    attn_weighted<<<wgrid, 256>>>(1);
    dec_fin<<<1, 256>>>(pHnR, 1, Wv, lin_W, lin_b, pos);

    // 5) child decode step (B=4)
    attn_init<<<1, 256>>>();
    dec_prep<<<4, 256>>>(emb, tgt, 1, pHr, pCnR,
                         W_ih, b_ih, W_hh, b_hh, Wq, Wk, pHnC, pCnC, pQkC);
    attn_scores<<<sgrid, 256>>>(pQkC, 4);
    attn_weighted<<<wgrid, 256>>>(4);
    dec_fin<<<4, 256>>>(pHnC, 0, Wv, lin_W, lin_b, pos);

    // 6) vocab projection
    out_proj<<<20, 256>>>(W_out, b_out, out);
}

// round 3
// speedup vs baseline: 2.0495x; 1.1321x over previous
#include <cuda_runtime.h>
#include <cstdint>

#define NROWS 87382          // 87381 nodes + duplicated root
#define NLEAF 65536
#define LEAF_SOFF 21845

#define NSTAGE 4
#define A_STG 5120           // 256 rows * 20 floats
#define W_STG 2560           // 128 rows * 20 floats
#define GEMM_SMEM ((NSTAGE*(A_STG+W_STG))*4)

// ---------------- device scratch (no allocations allowed) ----------------
__device__ float g_T_iou[1000*768];
__device__ float g_T_f[1000*256];
__device__ float g_uiou0[768];
__device__ float g_uf0[1024];
__device__ float g_lH[1000*256];
__device__ float g_lC[1000*256];
__device__ float g_U[1792*1024];            // packed [U_iou; U_f], tf32-rounded
__device__ float g_enc_h[(size_t)NROWS*256];
__device__ float g_hT[(size_t)NROWS*256];   // tf32-rounded copy of enc_h (GEMM A operand)
__device__ float g_cA[(size_t)NLEAF*256];
__device__ float g_cB[(size_t)16384*256];
__device__ float g_G[(size_t)16384*1792];   // combined gate preactivations
__device__ float g_sbuf[(size_t)4*NROWS];
__device__ float g_w[4*256];
__device__ float g_sum[4];
__device__ float g_max[4];
__device__ float g_hn_r[256];
__device__ float g_cn_r[256];
__device__ float g_qk_r[256];
__device__ float g_hn_c[4*256];
__device__ float g_cn_c[4*256];
__device__ float g_qk_c[4*256];
__device__ float g_hr[256];
__device__ float g_rows[20*256];

__device__ __forceinline__ float sigf(float x){ return 1.f/(1.f+__expf(-x)); }
__device__ __forceinline__ float tanhfast(float x){ return 1.f - 2.f/(__expf(2.f*x)+1.f); }

__device__ __forceinline__ float to_tf32(float x){
    uint32_t r;
    asm("cvt.rna.tf32.f32 %0, %1;" : "=r"(r) : "f"(x));
    return __uint_as_float(r);
}

__device__ __forceinline__ void atomicMaxFloat(float* addr, float val){
    int old = __float_as_int(*addr);
    while (__int_as_float(old) < val) {
        int assumed = old;
        old = atomicCAS((int*)addr, assumed, __float_as_int(val));
        if (old == assumed) break;
    }
}

__device__ __forceinline__ void cpasync16(uint32_t dst, const float* src, bool pred){
    int sz = pred ? 16 : 0;
    asm volatile("cp.async.cg.shared.global [%0], [%1], 16, %2;\n"
                 :: "r"(dst), "l"(src), "r"(sz));
}
__device__ __forceinline__ void cp_commit(){ asm volatile("cp.async.commit_group;\n"); }
template<int N> __device__ __forceinline__ void cp_wait(){ asm volatile("cp.async.wait_group %0;\n" :: "n"(N)); }

// ---------------- pack [U_iou; U_f] into one 1792x1024 matrix, tf32-rounded ----------------
__global__ void pack_U(const float* __restrict__ U_iou, const float* __restrict__ U_f)
{
    int idx = blockIdx.x * 256 + threadIdx.x;
    if (idx >= 1792*1024/4) return;
    int r = idx / 256;
    int c4 = idx % 256;
    const float4* srcp;
    if (r < 768) srcp = reinterpret_cast<const float4*>(U_iou + (size_t)r*1024) + c4;
    else         srcp = reinterpret_cast<const float4*>(U_f   + (size_t)(r-768)*1024) + c4;
    float4 v = *srcp;
    v.x = to_tf32(v.x); v.y = to_tf32(v.y); v.z = to_tf32(v.z); v.w = to_tf32(v.w);
    reinterpret_cast<float4*>(g_U + (size_t)r*1024)[c4] = v;
}

// ---------------- tf32 tensor-core GEMM: C[M,1792] = A[M,1024] @ U^T ----------------
// 256(M) x 128(N) tile, BK=16, 8 warps of 64x64, cp.async 4-stage pipeline.
// Inputs A and g_U are already tf32-RNA-rounded.
#define GK 1024
#define GN 1792
__global__ void __launch_bounds__(256, 1) gemm_tf32(
    const float* __restrict__ A, float* __restrict__ C, int M)
{
    extern __shared__ float sm[];
    float* Asm = sm;                    // NSTAGE * A_STG
    float* Wsm = sm + NSTAGE*A_STG;     // NSTAGE * W_STG

    const int tid  = threadIdx.x;
    const int lane = tid & 31;
    const int wid  = tid >> 5;
    const int warp_m = wid & 3;
    const int warp_n = wid >> 2;
    const int g  = lane >> 2;
    const int tq = lane & 3;

    const int m0 = blockIdx.y * 256;
    const int n0 = blockIdx.x * 128;

    const int am_row = m0 + tid;
    const bool aok = am_row < M;
    const float* Ars = A + (size_t)am_row * GK;
    const int wn  = n0 + (tid & 127);
    const int wc  = (tid >> 7) * 2;           // W chunk base: 0 or 2
    const float* Wrs = g_U + (size_t)wn * GK;

    uint32_t a_dst = (uint32_t)__cvta_generic_to_shared(Asm + tid*20);
    uint32_t w_dst = (uint32_t)__cvta_generic_to_shared(Wsm + (tid&127)*20 + wc*4);

    auto issue = [&](int slot, int k0){
        uint32_t ad = a_dst + slot*(A_STG*4);
        const float* as = Ars + k0;
        #pragma unroll
        for (int c = 0; c < 4; c++) cpasync16(ad + c*16, as + c*4, aok);
        uint32_t wd = w_dst + slot*(W_STG*4);
        const float* ws = Wrs + k0 + wc*4;
        #pragma unroll
        for (int c = 0; c < 2; c++) cpasync16(wd + c*16, ws + c*4, true);
        cp_commit();
    };

    #pragma unroll
    for (int s = 0; s < NSTAGE-1; s++) issue(s, s*16);

    float acc[4][8][4];
    #pragma unroll
    for (int mt = 0; mt < 4; mt++)
        #pragma unroll
        for (int nt = 0; nt < 8; nt++)
            #pragma unroll
            for (int q = 0; q < 4; q++) acc[mt][nt][q] = 0.f;

    const int NCH = GK/16;   // 64
    for (int i = 0; i < NCH; i++) {
        cp_wait<NSTAGE-2>();
        __syncthreads();
        const float* As = Asm + (i % NSTAGE)*A_STG;
        const float* Ws = Wsm + (i % NSTAGE)*W_STG;

        #pragma unroll
        for (int kk = 0; kk < 16; kk += 8) {
            uint32_t af[4][4], bf[8][2];
            #pragma unroll
            for (int mt = 0; mt < 4; mt++) {
                int rm = warp_m*64 + mt*16 + g;
                af[mt][0] = __float_as_uint(As[rm*20     + kk+tq  ]);
                af[mt][1] = __float_as_uint(As[(rm+8)*20 + kk+tq  ]);
                af[mt][2] = __float_as_uint(As[rm*20     + kk+tq+4]);
                af[mt][3] = __float_as_uint(As[(rm+8)*20 + kk+tq+4]);
            }
            #pragma unroll
            for (int nt = 0; nt < 8; nt++) {
                int cn = warp_n*64 + nt*8 + g;
                bf[nt][0] = __float_as_uint(Ws[cn*20 + kk+tq  ]);
                bf[nt][1] = __float_as_uint(Ws[cn*20 + kk+tq+4]);
            }
            #pragma unroll
            for (int mt = 0; mt < 4; mt++)
                #pragma unroll
                for (int nt = 0; nt < 8; nt++) {
                    asm volatile(
                        "mma.sync.aligned.m16n8k8.row.col.f32.tf32.tf32.f32 "
                        "{%0,%1,%2,%3}, {%4,%5,%6,%7}, {%8,%9}, {%0,%1,%2,%3};"
                        : "+f"(acc[mt][nt][0]), "+f"(acc[mt][nt][1]),
                          "+f"(acc[mt][nt][2]), "+f"(acc[mt][nt][3])
                        : "r"(af[mt][0]), "r"(af[mt][1]), "r"(af[mt][2]), "r"(af[mt][3]),
                          "r"(bf[nt][0]), "r"(bf[nt][1]));
                }
        }

        int nx = i + NSTAGE - 1;
        if (nx < NCH) issue(nx % NSTAGE, nx*16);
        else { cp_commit(); }   // keep group count consistent
    }

    #pragma unroll
    for (int mt = 0; mt < 4; mt++) {
        int m = m0 + warp_m*64 + mt*16 + g;
        #pragma unroll
        for (int nt = 0; nt < 8; nt++) {
            int n = n0 + warp_n*64 + nt*8 + tq*2;
            if (m < M)
                *reinterpret_cast<float2*>(C + (size_t)m*GN + n)
                    = make_float2(acc[mt][nt][0], acc[mt][nt][1]);
            if (m + 8 < M)
                *reinterpret_cast<float2*>(C + (size_t)(m+8)*GN + n)
                    = make_float2(acc[mt][nt][2], acc[mt][nt][3]);
        }
    }
}

// ---------------- small-M GEMM (M<=64): warp-per-column, fp32 ----------------
__global__ void small_gemm(const float* __restrict__ A, float* __restrict__ C)
{
    __shared__ float sh[1024];
    int tid = threadIdx.x, lane = tid & 31, wid = tid >> 5;
    int m = blockIdx.y;
    for (int i = tid; i < 256; i += 256)
        reinterpret_cast<float4*>(sh)[i] = reinterpret_cast<const float4*>(A + (size_t)m*1024)[i];
    __syncthreads();
    int ntile = blockIdx.x * 256;
    for (int n = ntile + wid; n < ntile + 256 && n < GN; n += 8) {
        const float4* u = reinterpret_cast<const float4*>(g_U + (size_t)n*1024);
        float acc = 0.f;
        #pragma unroll
        for (int i = 0; i < 8; i++) {
            float4 uv = u[lane + i*32];
            float4 hv = reinterpret_cast<const float4*>(sh)[lane + i*32];
            acc += uv.x*hv.x + uv.y*hv.y + uv.z*hv.z + uv.w*hv.w;
        }
        #pragma unroll
        for (int off = 16; off; off >>= 1) acc += __shfl_xor_sync(0xffffffffu, acc, off);
        if (lane == 0) C[(size_t)m*GN + n] = acc;
    }
}

// ---------------- SIMT NT GEMM (vocab tables) ----------------
__global__ void __launch_bounds__(256, 2) gemm_nt(
    const float* __restrict__ A, const float* __restrict__ W,
    const float* __restrict__ bias, const float* __restrict__ bias2,
    float* __restrict__ C, int M, int N, int K)
{
    __shared__ float As[16][128];
    __shared__ float Ws[16][128];
    const int tid  = threadIdx.x;
    const int m0   = blockIdx.y * 128;
    const int n0   = blockIdx.x * 128;
    const int trow = (tid >> 4) << 3;
    const int tcol = (tid & 15) << 3;
    const int lm   = tid >> 2;
    const int lk   = (tid & 3) << 2;

    float acc[8][8];
    #pragma unroll
    for (int i = 0; i < 8; i++)
        #pragma unroll
        for (int j = 0; j < 8; j++) acc[i][j] = 0.f;

    for (int k0 = 0; k0 < K; k0 += 16) {
        #pragma unroll
        for (int h = 0; h < 2; h++) {
            int m = m0 + lm + h*64;
            float4 v = make_float4(0.f,0.f,0.f,0.f);
            if (m < M) v = *reinterpret_cast<const float4*>(A + (size_t)m*K + k0 + lk);
            As[lk+0][lm+h*64] = v.x; As[lk+1][lm+h*64] = v.y;
            As[lk+2][lm+h*64] = v.z; As[lk+3][lm+h*64] = v.w;

            int n = n0 + lm + h*64;
            float4 w = make_float4(0.f,0.f,0.f,0.f);
            if (n < N) w = *reinterpret_cast<const float4*>(W + (size_t)n*K + k0 + lk);
            Ws[lk+0][lm+h*64] = w.x; Ws[lk+1][lm+h*64] = w.y;
            Ws[lk+2][lm+h*64] = w.z; Ws[lk+3][lm+h*64] = w.w;
        }
        __syncthreads();
        #pragma unroll
        for (int kk = 0; kk < 16; kk++) {
            float ra[8], rw[8];
            #pragma unroll
            for (int i = 0; i < 8; i++) ra[i] = As[kk][trow+i];
            #pragma unroll
            for (int j = 0; j < 8; j++) rw[j] = Ws[kk][tcol+j];
            #pragma unroll
            for (int i = 0; i < 8; i++)
                #pragma unroll
                for (int j = 0; j < 8; j++) acc[i][j] += ra[i]*rw[j];
        }
        __syncthreads();
    }
    #pragma unroll
    for (int i = 0; i < 8; i++) {
        int m = m0 + trow + i;
        if (m >= M) break;
        #pragma unroll
        for (int j = 0; j < 8; j++) {
            int n = n0 + tcol + j;
            float b = 0.f;
            if (bias)  b += bias[n];
            if (bias2) b += bias2[n];
            C[(size_t)m*N + n] = acc[i][j] + b;
        }
    }
}

// ---------------- leaf constants: warp per output ----------------
__global__ void leaf_consts(const float* __restrict__ h0, const float* __restrict__ U_iou,
                            const float* __restrict__ U_f, const float* __restrict__ b_uf)
{
    int lane = threadIdx.x & 31;
    int w = blockIdx.x * 8 + (threadIdx.x >> 5);   // 0..1791
    const float* u;
    float acc = 0.f;
    if (w < 768) u = U_iou + (size_t)w*1024;
    else { u = U_f + (size_t)(w-768)*1024; }
    const float4* u4 = reinterpret_cast<const float4*>(u);
    const float4* h4 = reinterpret_cast<const float4*>(h0);
    #pragma unroll
    for (int i = 0; i < 8; i++) {
        float4 uv = u4[lane + i*32];
        float4 hv = h4[lane + i*32];
        acc += uv.x*hv.x + uv.y*hv.y + uv.z*hv.z + uv.w*hv.w;
    }
    #pragma unroll
    for (int off = 16; off; off >>= 1) acc += __shfl_xor_sync(0xffffffffu, acc, off);
    if (lane == 0) {
        if (w < 768) g_uiou0[w] = acc;
        else g_uf0[w-768] = acc + b_uf[w-768];
    }
}

// ---------------- per-symbol leaf tables: h,c for each of 1000 symbols ----------------
__global__ void leaf_tab(const float* __restrict__ c0)
{
    int s = blockIdx.x, j = threadIdx.x;
    const float* T = g_T_iou + (size_t)s*768;
    float i = sigf(T[j]       + g_uiou0[j]);
    float o = sigf(T[256+j]   + g_uiou0[256+j]);
    float u = tanhfast(T[512+j] + g_uiou0[512+j]);
    float tf = g_T_f[(size_t)s*256 + j];
    float c = i*u;
    #pragma unroll
    for (int a = 0; a < 4; a++) {
        float f = sigf(g_uf0[a*256+j] + tf);
        c += f * c0[a*256+j];
    }
    g_lH[(size_t)s*256 + j] = o * tanhfast(c);
    g_lC[(size_t)s*256 + j] = c;
}

// ---------------- leaf level: pure float4 gather ----------------
__global__ void leaf_gather(const int* __restrict__ src)
{
    int node = blockIdx.x * 4 + (threadIdx.x >> 6);
    int j4 = threadIdx.x & 63;
    int id = src[LEAF_SOFF + node];
    float4 h = reinterpret_cast<const float4*>(g_lH + (size_t)id*256)[j4];
    float4 c = reinterpret_cast<const float4*>(g_lC + (size_t)id*256)[j4];
    reinterpret_cast<float4*>(g_enc_h + (size_t)node*256)[j4] = h;
    reinterpret_cast<float4*>(g_cA    + (size_t)node*256)[j4] = c;
    float4 ht = make_float4(to_tf32(h.x), to_tf32(h.y), to_tf32(h.z), to_tf32(h.w));
    reinterpret_cast<float4*>(g_hT + (size_t)node*256)[j4] = ht;
}

// ---------------- interior level: combine GEMM result + gates ----------------
__global__ void level_ew(const int* __restrict__ src, int soff,
                         const float* __restrict__ cprev, float* __restrict__ cout,
                         int rowoff, int dup, const float* __restrict__ b_uf)
{
    int b = blockIdx.x, j = threadIdx.x;
    int id = src[soff + b];
    const float* T = g_T_iou + (size_t)id*768;
    const float* G = g_G + (size_t)b*1792;
    float i = sigf(G[j]       + T[j]);
    float o = sigf(G[256+j]   + T[256+j]);
    float u = tanhfast(G[512+j] + T[512+j]);
    float tf = g_T_f[(size_t)id*256 + j];
    float c = i*u;
    #pragma unroll
    for (int a = 0; a < 4; a++) {
        float f = sigf(G[768 + a*256 + j] + b_uf[a*256+j] + tf);
        c += f * cprev[(size_t)(4*b+a)*256 + j];
    }
    float h = o * tanhfast(c);
    g_enc_h[(size_t)(rowoff+b)*256 + j] = h;
    g_hT[(size_t)(rowoff+b)*256 + j]   = to_tf32(h);
    cout[(size_t)b*256 + j] = c;
    if (dup) g_enc_h[(size_t)(rowoff+1)*256 + j] = h;   // duplicate root row
}

// ---------------- decoder LSTM cell + fused q@Wq@Wk ----------------
__global__ void dec_prep(const float* __restrict__ emb, const int* __restrict__ tgt, int tbase,
                         const float* __restrict__ h_last, const float* __restrict__ c_last,
                         const float* __restrict__ W_ih, const float* __restrict__ b_ih,
                         const float* __restrict__ W_hh, const float* __restrict__ b_hh,
                         const float* __restrict__ Wq,   const float* __restrict__ Wk,
                         float* __restrict__ hn_out, float* __restrict__ cn_out,
                         float* __restrict__ qk_out)
{
    __shared__ float sx[256], sh[256], shn[256], sq[256];
    int j = threadIdx.x, bb = blockIdx.x;
    int sym = tgt[tbase + bb];
    sx[j] = emb[(size_t)sym*256 + j];
    sh[j] = h_last[j];
    __syncthreads();
    float g[4];
    #pragma unroll
    for (int p = 0; p < 4; p++) {
        int row = p*256 + j;
        const float* wi = W_ih + (size_t)row*256;
        const float* wh = W_hh + (size_t)row*256;
        float acc = b_ih[row] + b_hh[row];
        for (int k = 0; k < 256; k++) acc += sx[k]*wi[k] + sh[k]*wh[k];
        g[p] = acc;
    }
    float cn = sigf(g[1])*c_last[j] + sigf(g[0])*tanhfast(g[2]);
    float hn = sigf(g[3])*tanhfast(cn);
    shn[j] = hn;
    hn_out[bb*256+j] = hn;
    cn_out[bb*256+j] = cn;
    __syncthreads();
    const float* wq = Wq + (size_t)j*256;
    float q = 0.f;
    for (int k = 0; k < 256; k++) q += shn[k]*wq[k];
    sq[j] = q;
    __syncthreads();
    float qk = 0.f;
    for (int k = 0; k < 256; k++) qk += sq[k]*Wk[(size_t)k*256 + j];
    qk_out[bb*256+j] = qk;
}

__global__ void attn_init()
{
    int t = threadIdx.x;
    for (int i = t; i < 4*256; i += 256) g_w[i] = 0.f;
    if (t < 4) { g_sum[t] = 0.f; g_max[t] = -1e30f; }
}

#define SROWS 512
__global__ void attn_scores(const float* __restrict__ qk, int B)
{
    __shared__ float sqk[4*256];
    __shared__ float wmax[8*4];
    int tid = threadIdx.x;
    for (int i = tid; i < B*256; i += 256) sqk[i] = qk[i];
    __syncthreads();
    int warp = tid >> 5, lane = tid & 31;
    int start = blockIdx.x * SROWS;
    int end = min(NROWS, start + SROWS);
    float lmax[4] = {-1e30f,-1e30f,-1e30f,-1e30f};
    for (int r = start + warp; r < end; r += 8) {
        const float4* eh = reinterpret_cast<const float4*>(g_enc_h + (size_t)r*256) + lane*2;
        float4 v0 = eh[0], v1 = eh[1];
        #pragma unroll 4
        for (int b = 0; b < 4; b++) {
            if (b >= B) break;
            const float* q = sqk + b*256 + lane*8;
            float acc = v0.x*q[0]+v0.y*q[1]+v0.z*q[2]+v0.w*q[3]
                      + v1.x*q[4]+v1.y*q[5]+v1.z*q[6]+v1.w*q[7];
            #pragma unroll
            for (int off = 16; off; off >>= 1) acc += __shfl_xor_sync(0xffffffffu, acc, off);
            if (lane == 0) g_sbuf[(size_t)b*NROWS + r] = acc;
            lmax[b] = fmaxf(lmax[b], acc);
        }
    }
    if (lane == 0)
        for (int b = 0; b < 4; b++) wmax[warp*4+b] = lmax[b];
    __syncthreads();
    if (tid < B) {
        float m = -1e30f;
        for (int w = 0; w < 8; w++) m = fmaxf(m, wmax[w*4+tid]);
        atomicMaxFloat(&g_max[tid], m);
    }
}

#define WROWS 256
__global__ void attn_weighted(int B)
{
    __shared__ float se[4*64];
    int tid = threadIdx.x;
    float mx[4] = {0,0,0,0};
    for (int b = 0; b < B; b++) mx[b] = g_max[b];
    float wloc[4] = {0,0,0,0};
    float ssum = 0.f;
    int start = blockIdx.x * WROWS;
    int end = min(NROWS, start + WROWS);
    for (int c0 = start; c0 < end; c0 += 64) {
        int nr = end - c0; if (nr > 64) nr = 64;
        __syncthreads();
        if (tid < 64*B) {
            int b = tid >> 6, i = tid & 63;
            se[tid] = (i < nr) ? __expf(g_sbuf[(size_t)b*NROWS + c0 + i] - mx[b]) : 0.f;
        }
        __syncthreads();
        for (int i = 0; i < nr; i++) {
            float x = g_enc_h[(size_t)(c0+i)*256 + tid];
            #pragma unroll 4
            for (int b = 0; b < 4; b++) {
                if (b >= B) break;
                wloc[b] += se[b*64+i]*x;
            }
        }
        if (tid < B)
            for (int i = 0; i < nr; i++) ssum += se[tid*64+i];
    }
    for (int b = 0; b < B; b++) atomicAdd(&g_w[b*256+tid], wloc[b]);
    if (tid < B) atomicAdd(&g_sum[tid], ssum);
}

__global__ void dec_fin(const float* __restrict__ hn, int is_root,
                        const float* __restrict__ Wv, const float* __restrict__ linW,
                        const float* __restrict__ linb, const float* __restrict__ pos)
{
    __shared__ float swb[256], sctx[256], shn[256];
    int b = blockIdx.x, j = threadIdx.x;
    swb[j] = g_w[b*256+j] / g_sum[b];
    shn[j] = hn[b*256+j];
    __syncthreads();
    const float* wv = Wv + (size_t)j*256;
    float acc = 0.f;
    for (int k = 0; k < 256; k++) acc += swb[k]*wv[k];
    sctx[j] = acc;
    __syncthreads();
    const float* lw = linW + (size_t)j*512;
    float ho = linb[j];
    for (int k = 0; k < 256; k++) ho += shn[k]*lw[k];
    for (int k = 0; k < 256; k++) ho += sctx[k]*lw[256+k];
    if (is_root) {
        g_hr[j] = ho;
        #pragma unroll
        for (int a = 0; a < 4; a++) g_rows[a*256+j] = ho + pos[a*256+j];
    } else {
        #pragma unroll
        for (int a = 0; a < 4; a++) g_rows[(4 + b*4 + a)*256 + j] = ho + pos[a*256+j];
    }
}

__global__ void out_proj(const float* __restrict__ Wout, const float* __restrict__ bout,
                         float* __restrict__ out)
{
    __shared__ float sr[256];
    int j = threadIdx.x;
    sr[j] = g_rows[blockIdx.x*256 + j];
    __syncthreads();
    for (int n = j; n < 1000; n += 256) {
        const float* w = Wout + (size_t)n*256;
        float acc = bout[n];
        for (int k = 0; k < 256; k++) acc += sr[k]*w[k];
        out[blockIdx.x*1000 + n] = acc;
    }
}

// ---------------------------------------------------------------------------
extern "C" void kernel_launch(void* const* d_in, const int* in_sizes, int n_in,
                              void* d_out, int out_size)
{
    const int*   src    = (const int*)  d_in[0];
    const int*   tgt    = (const int*)  d_in[1];
    const float* emb    = (const float*)d_in[2];
    const float* h0     = (const float*)d_in[3];
    const float* c0     = (const float*)d_in[4];
    const float* W_iou  = (const float*)d_in[5];
    const float* b_iou  = (const float*)d_in[6];
    const float* U_iou  = (const float*)d_in[7];
    const float* b_uiou = (const float*)d_in[8];
    const float* W_f    = (const float*)d_in[9];
    const float* b_wf   = (const float*)d_in[10];
    const float* U_f    = (const float*)d_in[11];
    const float* b_uf   = (const float*)d_in[12];
    const float* W_ih   = (const float*)d_in[13];
    const float* b_ih   = (const float*)d_in[14];
    const float* W_hh   = (const float*)d_in[15];
    const float* b_hh   = (const float*)d_in[16];
    const float* Wq     = (const float*)d_in[17];
    const float* Wk     = (const float*)d_in[18];
    const float* Wv     = (const float*)d_in[19];
    const float* lin_W  = (const float*)d_in[20];
    const float* lin_b  = (const float*)d_in[21];
    const float* pos    = (const float*)d_in[22];
    const float* W_out  = (const float*)d_in[23];
    const float* b_out  = (const float*)d_in[24];
    float* out = (float*)d_out;

    static bool attr_done = false;
    if (!attr_done) {
        cudaFuncSetAttribute(gemm_tf32, cudaFuncAttributeMaxDynamicSharedMemorySize, GEMM_SMEM);
        attr_done = true;
    }

    float *pTiou,*pTf,*pEnc,*pHT,*pCA,*pCB,*pG;
    float *pHnR,*pCnR,*pQkR,*pHnC,*pCnC,*pQkC,*pHr;
    cudaGetSymbolAddress((void**)&pTiou, g_T_iou);
    cudaGetSymbolAddress((void**)&pTf,   g_T_f);
    cudaGetSymbolAddress((void**)&pEnc,  g_enc_h);
    cudaGetSymbolAddress((void**)&pHT,   g_hT);
    cudaGetSymbolAddress((void**)&pCA,   g_cA);
    cudaGetSymbolAddress((void**)&pCB,   g_cB);
    cudaGetSymbolAddress((void**)&pG,    g_G);
    cudaGetSymbolAddress((void**)&pHnR,  g_hn_r);
    cudaGetSymbolAddress((void**)&pCnR,  g_cn_r);
    cudaGetSymbolAddress((void**)&pQkR,  g_qk_r);
    cudaGetSymbolAddress((void**)&pHnC,  g_hn_c);
    cudaGetSymbolAddress((void**)&pCnC,  g_cn_c);
    cudaGetSymbolAddress((void**)&pQkC,  g_qk_c);
    cudaGetSymbolAddress((void**)&pHr,   g_hr);

    static const int pow4[10] = {1,4,16,64,256,1024,4096,16384,65536,262144};
    auto rowoff = [&](int l){ return (262144 - pow4[l+1]) / 3; };
    auto soff   = [&](int l){ return (pow4[l] - 1) / 3; };

    // 1) per-vocab tables + packed/rounded U + leaf constants
    gemm_nt<<<dim3(6, 8), 256>>>(emb, W_iou, b_iou, b_uiou, pTiou, 1000, 768, 256);
    gemm_nt<<<dim3(2, 8), 256>>>(emb, W_f,   b_wf,  nullptr, pTf,   1000, 256, 256);
    pack_U<<<(1792*1024/4 + 255)/256, 256>>>(U_iou, U_f);
    leaf_consts<<<224, 256>>>(h0, U_iou, U_f, b_uf);

    // 2) symbol tables + leaf gather
    leaf_tab<<<1000, 256>>>(c0);
    leaf_gather<<<NLEAF/4, 256>>>(src);

    // 3) interior levels bottom-up
    float* cprev = pCA;
    float* cout  = pCB;
    for (int l = 7; l >= 0; l--) {
        int B = pow4[l];
        if (B >= 256) {
            const float* Ap = pHT + (size_t)rowoff(l+1)*256;
            gemm_tf32<<<dim3(14, (B+255)/256), 256, GEMM_SMEM>>>(Ap, pG, B);
        } else {
            const float* Ap = pEnc + (size_t)rowoff(l+1)*256;
            small_gemm<<<dim3(7, B), 256>>>(Ap, pG);
        }
        level_ew<<<B, 256>>>(src, soff(l), cprev, cout, rowoff(l), (l == 0) ? 1 : 0, b_uf);
        float* t = cprev; cprev = cout; cout = t;
    }

    int sgrid = (NROWS + SROWS - 1) / SROWS;
    int wgrid = (NROWS + WROWS - 1) / WROWS;

    // 4) root decode step
    attn_init<<<1, 256>>>();
    dec_prep<<<1, 256>>>(emb, tgt, 0, pEnc + (size_t)(NROWS-1)*256, cprev,
                         W_ih, b_ih, W_hh, b_hh, Wq, Wk, pHnR, pCnR, pQkR);
    attn_scores<<<sgrid, 256>>>(pQkR, 1);
    attn_weighted<<<wgrid, 256>>>(1);
    dec_fin<<<1, 256>>>(pHnR, 1, Wv, lin_W, lin_b, pos);

    // 5) child decode step (B=4)
    attn_init<<<1, 256>>>();
    dec_prep<<<4, 256>>>(emb, tgt, 1, pHr, pCnR,
                         W_ih, b_ih, W_hh, b_hh, Wq, Wk, pHnC, pCnC, pQkC);
    attn_scores<<<sgrid, 256>>>(pQkC, 4);
    attn_weighted<<<wgrid, 256>>>(4);
    dec_fin<<<4, 256>>>(pHnC, 0, Wv, lin_W, lin_b, pos);

    // 6) vocab projection
    out_proj<<<20, 256>>>(W_out, b_out, out);
}